// round 3
// baseline (speedup 1.0000x reference)
#include <cuda_runtime.h>

// out[b,i,d] = x[b,i] * W[i,d] + b[i,d]
// B=128, N=1024, D=512 fp32. Pure HBM-write-bound: 268MB out, 4.5MB in.
//
// Single-wave layout: grid = N = 1024 blocks (< 148 SMs x 8 occ = 1184, so
// ONE wave, zero wave transitions). Each block owns one neuron row i:
//   - W[i,:], b[i,:] loaded into registers exactly once (minimum read traffic)
//   - x[:, i] (128 floats) staged into smem once, broadcast-LDS in the loop
//   - 128 coalesced 2KB row stores with streaming hint (__stcs) so the
//     output doesn't evict W/b from L2.

#define BB 128
#define NN 1024
#define DD 512
#define D4 (DD / 4)          // 128 float4 per row == blockDim

__global__ __launch_bounds__(D4, 8)
void fused_scalar_linear_kernel(const float* __restrict__ x,
                                const float4* __restrict__ W,
                                const float4* __restrict__ bias,
                                float4* __restrict__ out) {
    __shared__ float xs[BB];

    const int i  = blockIdx.x;       // neuron row 0..NN-1
    const int d4 = threadIdx.x;      // 0..D4-1 (==128 threads)

    // Stage the whole x column for this row: thread t fetches batch t.
    // (BB == blockDim == 128, so one load per thread covers it.)
    xs[d4] = __ldg(&x[(size_t)d4 * NN + i]);

    // One-time register load of this thread's W/b slice.
    const float4 w  = W[i * D4 + d4];
    const float4 bv = bias[i * D4 + d4];

    __syncthreads();

    // Base pointer for this thread's output column; batch stride = NN*D4 float4.
    float4* __restrict__ o_base = out + (size_t)i * D4 + d4;

    #pragma unroll 8
    for (int k = 0; k < BB; ++k) {
        const float xv = xs[k];      // broadcast LDS, conflict-free
        float4 o;
        o.x = fmaf(xv, w.x, bv.x);
        o.y = fmaf(xv, w.y, bv.y);
        o.z = fmaf(xv, w.z, bv.z);
        o.w = fmaf(xv, w.w, bv.w);
        // Streaming store: evict-first, keep W/b resident in L2.
        __stcs(o_base + (size_t)k * (NN * D4), o);
    }
}

extern "C" void kernel_launch(void* const* d_in, const int* in_sizes, int n_in,
                              void* d_out, int out_size) {
    const float*  x    = (const float*)d_in[0];   // [B, N, 1]
    const float4* W    = (const float4*)d_in[1];  // [N, D]
    const float4* bias = (const float4*)d_in[2];  // [N, D]
    float4* out = (float4*)d_out;                 // [B, N, D]

    fused_scalar_linear_kernel<<<NN, D4>>>(x, W, bias, out);
}